// round 17
// baseline (speedup 1.0000x reference)
#include <cuda_runtime.h>
#include <cstdint>

#define NSEG   512
#define HID    512
#define GOALD  128
#define INDIM  640
#define BLOCK  512
#define MROWS  1024         // nodes per block (2 per thread)
#define KT     16           // k tile (floats) = 64B rows
#define XPAD   20           // words per row (80B): conflict-free LDS.128
#define NTILES (INDIM / KT) // 40
#define XTILE_W  (MROWS * XPAD)          // 20480 words = 80KB per slot
#define WTILE_W  (KT * 16)               // 256 words = 1KB per slot
#define OFF_W_W  (2 * XTILE_W)           // word offset of W ring
#define SMEM_BYTES ((2 * XTILE_W + 2 * WTILE_W) * 4)   // 165888 B

typedef unsigned long long u64;

__device__ float    g_sum[NSEG];
__device__ float    g_cnt[NSEG];
__device__ unsigned g_max[NSEG];
__device__ unsigned g_done;

__device__ __forceinline__ void ffma2(u64 &acc, u64 a, u64 b) {
    asm("fma.rn.f32x2 %0, %1, %2, %0;" : "+l"(acc) : "l"(a), "l"(b));
}
__device__ __forceinline__ u64 pk2(float v) {
    u64 r; asm("mov.b64 %0, {%1, %1};" : "=l"(r) : "f"(v)); return r;
}
__device__ __forceinline__ float2 upk(u64 v) {
    float2 f; asm("mov.b64 {%0, %1}, %2;" : "=f"(f.x), "=f"(f.y) : "l"(v)); return f;
}
__device__ __forceinline__ void cp16(uint32_t dst, const void* src, bool pred) {
    int sz = pred ? 16 : 0;   // src_size 0 -> zero-fill
    asm volatile("cp.async.cg.shared.global [%0], [%1], 16, %2;"
                 :: "r"(dst), "l"(src), "r"(sz));
}
__device__ __forceinline__ void cp_commit() { asm volatile("cp.async.commit_group;"); }
template <int M> __device__ __forceinline__ void cp_wait() {
    asm volatile("cp.async.wait_group %0;" :: "n"(M));
}

__global__ __launch_bounds__(BLOCK, 1) void mlp_seg_kernel(
    const float* __restrict__ nodes, const float* __restrict__ goal,
    const int* __restrict__ segids,
    const float* __restrict__ W1, const float* __restrict__ b1,
    const float* __restrict__ W2, const float* __restrict__ b2,
    float* __restrict__ out, int N, int grid)
{
    extern __shared__ float smem[];
    const uint32_t sb = (uint32_t)__cvta_generic_to_shared(smem);
    const int t    = threadIdx.x;
    const int base = blockIdx.x * MROWS;

    // ---- staging: 1024 rows x 64B (4x16B chunks) into padded 80B rows ----
    // task = i*512+t : row = task>>2, ch = task&3
    auto stage = [&](int tile) {
        const int k0 = tile * KT;
        const float* src; int stride, kloc;
        if (k0 < HID) { src = nodes; stride = HID;   kloc = k0; }
        else          { src = goal;  stride = GOALD; kloc = k0 - HID; }
        uint32_t xb = sb + (uint32_t)(((tile & 1) * XTILE_W) << 2);
#pragma unroll
        for (int i = 0; i < 8; ++i) {
            int task = i * BLOCK + t;
            int row  = task >> 2, ch = task & 3;
            int node = base + row;
            cp16(xb + (uint32_t)(row * (XPAD * 4) + ch * 16),
                 src + (size_t)node * stride + kloc + ch * 4, node < N);
        }
        if (t < 64)
            cp16(sb + (uint32_t)(((OFF_W_W + (tile & 1) * WTILE_W) << 2) + t * 16),
                 W1 + k0 * 16 + t * 4, true);
        cp_commit();
    };

    u64 accA[8], accB[8];
#pragma unroll
    for (int p = 0; p < 8; ++p) { accA[p] = 0ull; accB[p] = 0ull; }

    stage(0);
    stage(1);

    const float* xrowA = smem + t * XPAD;                    // row t
    const float* xrowB = smem + (t + BLOCK) * XPAD;          // row t+512

#pragma unroll 1
    for (int tile = 0; tile < NTILES; ++tile) {
        if (tile == NTILES - 1) cp_wait<0>();   // final tile: drain fully
        else                    cp_wait<1>();
        __syncthreads();

        const int   boff = (tile & 1) * XTILE_W;
        const float* wtil = smem + OFF_W_W + (tile & 1) * WTILE_W;
#pragma unroll
        for (int kk = 0; kk < KT; kk += 4) {
            float4 xa = *(const float4*)(xrowA + boff + kk);
            float4 xb = *(const float4*)(xrowB + boff + kk);
#pragma unroll
            for (int r = 0; r < 4; ++r) {
                const ulonglong2* wr = (const ulonglong2*)(wtil + (kk + r) * 16);
                ulonglong2 w0 = wr[0], w1 = wr[1], w2 = wr[2], w3 = wr[3];
                float fa = (r == 0) ? xa.x : (r == 1) ? xa.y : (r == 2) ? xa.z : xa.w;
                float fb = (r == 0) ? xb.x : (r == 1) ? xb.y : (r == 2) ? xb.z : xb.w;
                u64 va = pk2(fa), vb = pk2(fb);
                ffma2(accA[0], va, w0.x); ffma2(accA[1], va, w0.y);
                ffma2(accA[2], va, w1.x); ffma2(accA[3], va, w1.y);
                ffma2(accA[4], va, w2.x); ffma2(accA[5], va, w2.y);
                ffma2(accA[6], va, w3.x); ffma2(accA[7], va, w3.y);
                ffma2(accB[0], vb, w0.x); ffma2(accB[1], vb, w0.y);
                ffma2(accB[2], vb, w1.x); ffma2(accB[3], vb, w1.y);
                ffma2(accB[4], vb, w2.x); ffma2(accB[5], vb, w2.y);
                ffma2(accB[6], vb, w3.x); ffma2(accB[7], vb, w3.y);
            }
        }
        __syncthreads();                 // all warps done reading this slot
        if (tile + 2 < NTILES) stage(tile + 2);   // refill (async, overlaps)
    }

    // --- epilogue: thread owns ALL 16 j for rows t and t+512 ---
    float w2r[16], b1r[16];
#pragma unroll
    for (int j = 0; j < 16; ++j) { b1r[j] = b1[j]; w2r[j] = W2[j]; }
    const float bias2 = b2[0];

#pragma unroll
    for (int n = 0; n < 2; ++n) {
        u64* acc = n ? accB : accA;
        int node = base + t + n * BLOCK;
        if (node < N) {
            float o = bias2;
#pragma unroll
            for (int p = 0; p < 8; ++p) {
                float2 a = upk(acc[p]);
                o += fmaxf(a.x + b1r[2 * p],     0.f) * w2r[2 * p];
                o += fmaxf(a.y + b1r[2 * p + 1], 0.f) * w2r[2 * p + 1];
            }
            int seg = segids[node];
            atomicAdd(&g_sum[seg], o);
            atomicAdd(&g_cnt[seg], 1.f);
            unsigned b = __float_as_uint(o);
            unsigned e = (b & 0x80000000u) ? ~b : (b | 0x80000000u);
            atomicMax(&g_max[seg], e);
        }
    }

    // --- last block finalizes ---
    __threadfence();
    __shared__ unsigned s_last;
    if (t == 0) s_last = (atomicAdd(&g_done, 1) == (unsigned)(grid - 1)) ? 1u : 0u;
    __syncthreads();
    if (s_last && t < NSEG) {
        float sum = __ldcg(&g_sum[t]);
        float cnt = __ldcg(&g_cnt[t]);
        unsigned u = __ldcg(&g_max[t]);
        float mean = sum / fmaxf(cnt, 1.f);
        float mx = (u & 0x80000000u) ? __uint_as_float(u ^ 0x80000000u)
                                     : __uint_as_float(~u);
        out[t] = mx * 0.5f + mean * 0.5f;
        g_sum[t] = 0.f; g_cnt[t] = 0.f; g_max[t] = 0u;
        __threadfence();
        if (t == 0) g_done = 0;
    }
}

extern "C" void kernel_launch(void* const* d_in, const int* in_sizes, int n_in,
                              void* d_out, int out_size) {
    const float* nodes  = (const float*)d_in[0];
    const float* goal   = (const float*)d_in[1];
    const int*   segids = (const int*)d_in[2];
    int iW = (in_sizes[3] == INDIM * 16) ? 3 : 4;   // num_segments may be absent
    const float* W1 = (const float*)d_in[iW];
    const float* b1 = (const float*)d_in[iW + 1];
    const float* W2 = (const float*)d_in[iW + 2];
    const float* b2 = (const float*)d_in[iW + 3];
    const int N = in_sizes[2];

    cudaFuncSetAttribute(mlp_seg_kernel,
                         cudaFuncAttributeMaxDynamicSharedMemorySize, SMEM_BYTES);
    int grid = (N + MROWS - 1) / MROWS;
    mlp_seg_kernel<<<grid, BLOCK, SMEM_BYTES>>>(nodes, goal, segids,
                                                W1, b1, W2, b2,
                                                (float*)d_out, N, grid);
}